// round 3
// baseline (speedup 1.0000x reference)
#include <cuda_runtime.h>
#include <cuda_bf16.h>
#include <cstdint>

// Problem constants
#define B       4
#define NSEQ    4096
#define DIM     1024
#define HEADS   8
#define DH      64
#define INNER   512          // HEADS*DH
#define M_ROWS  (B*NSEQ)     // 16384
#define N_QKV   (3*INNER)    // 1536
#define NCHUNK  8            // split-K chunks for context
#define ROWS_PER_CHUNK (NSEQ/NCHUNK)  // 512

// Scratch (device globals; no allocation allowed)
__device__ float g_qkv [(size_t)M_ROWS * N_QKV];          // ~100.7 MB
__device__ float g_ctxp[NCHUNK * B*HEADS * DH * DH];      // 4 MB partial contexts
__device__ float g_attn[(size_t)M_ROWS * INNER];          // ~33.5 MB

// ---------------------------------------------------------------------------
// SGEMM (NT):  C[M,N] = A[M,K] @ B[N,K]^T  (+ bias[N] if bias != nullptr)
// BM=BN=128, BK=16, 256 threads, 8x8 per-thread microtile.
// Requires M%128==0, N%128==0, K%16==0 (true for all our shapes).
// ---------------------------------------------------------------------------
#define BM 128
#define BN 128
#define BK 16
#define TM 8
#define TN 8

__global__ __launch_bounds__(256) void sgemm_nt(
    const float* __restrict__ A,
    const float* __restrict__ Bm,
    float* __restrict__ C,
    const float* __restrict__ bias,
    int M, int N, int K)
{
    __shared__ __align__(16) float As[BK][BM];
    __shared__ __align__(16) float Bs[BK][BN];

    const int bm  = blockIdx.y * BM;
    const int bn  = blockIdx.x * BN;
    const int tid = threadIdx.x;

    const int tx   = tid & 15;        // 16 thread-cols
    const int ty   = tid >> 4;        // 16 thread-rows
    const int row0 = ty * TM;
    const int col0 = tx * TN;

    float acc[TM][TN];
    #pragma unroll
    for (int i = 0; i < TM; i++)
        #pragma unroll
        for (int j = 0; j < TN; j++)
            acc[i][j] = 0.f;

    const float* Aptr = A  + (size_t)bm * K;
    const float* Bptr = Bm + (size_t)bn * K;

    for (int k0 = 0; k0 < K; k0 += BK) {
        // stage tiles: 512 float4 per operand, 2 per thread
        #pragma unroll
        for (int i = 0; i < 2; i++) {
            int id = tid + i * 256;          // 0..511
            int r  = id >> 2;                // row in tile 0..127
            int kk = (id & 3) * 4;           // k offset 0..12
            float4 av = *(const float4*)(Aptr + (size_t)r * K + k0 + kk);
            As[kk+0][r] = av.x; As[kk+1][r] = av.y;
            As[kk+2][r] = av.z; As[kk+3][r] = av.w;
            float4 bv = *(const float4*)(Bptr + (size_t)r * K + k0 + kk);
            Bs[kk+0][r] = bv.x; Bs[kk+1][r] = bv.y;
            Bs[kk+2][r] = bv.z; Bs[kk+3][r] = bv.w;
        }
        __syncthreads();

        #pragma unroll
        for (int kk = 0; kk < BK; kk++) {
            float a_frag[TM], b_frag[TN];
            float4 a0 = *(const float4*)&As[kk][row0];
            float4 a1 = *(const float4*)&As[kk][row0 + 4];
            a_frag[0]=a0.x; a_frag[1]=a0.y; a_frag[2]=a0.z; a_frag[3]=a0.w;
            a_frag[4]=a1.x; a_frag[5]=a1.y; a_frag[6]=a1.z; a_frag[7]=a1.w;
            float4 b0 = *(const float4*)&Bs[kk][col0];
            float4 b1 = *(const float4*)&Bs[kk][col0 + 4];
            b_frag[0]=b0.x; b_frag[1]=b0.y; b_frag[2]=b0.z; b_frag[3]=b0.w;
            b_frag[4]=b1.x; b_frag[5]=b1.y; b_frag[6]=b1.z; b_frag[7]=b1.w;
            #pragma unroll
            for (int i = 0; i < TM; i++)
                #pragma unroll
                for (int j = 0; j < TN; j++)
                    acc[i][j] += a_frag[i] * b_frag[j];
        }
        __syncthreads();
    }

    float bv[TN];
    #pragma unroll
    for (int j = 0; j < TN; j++)
        bv[j] = bias ? bias[bn + col0 + j] : 0.f;

    #pragma unroll
    for (int i = 0; i < TM; i++) {
        float* crow = C + (size_t)(bm + row0 + i) * N + bn + col0;
        float4 v0 = make_float4(acc[i][0]+bv[0], acc[i][1]+bv[1],
                                acc[i][2]+bv[2], acc[i][3]+bv[3]);
        float4 v1 = make_float4(acc[i][4]+bv[4], acc[i][5]+bv[5],
                                acc[i][6]+bv[6], acc[i][7]+bv[7]);
        *(float4*)(crow)     = v0;
        *(float4*)(crow + 4) = v1;
    }
}

// ---------------------------------------------------------------------------
// Context kernel: for each (b,h), ctx[d][e] = sum_n softmax(k[n,:])[d] * v[n,e]
// Split over n into NCHUNK chunks; each block writes a deterministic partial.
// grid = (32 pairs, NCHUNK), block = 256.
// ---------------------------------------------------------------------------
__global__ __launch_bounds__(256) void ctx_kernel()
{
    const int pair  = blockIdx.x;           // b*HEADS + h
    const int chunk = blockIdx.y;
    const int b = pair >> 3, h = pair & 7;
    const int tid = threadIdx.x;

    __shared__ __align__(16) float sk[32][DH];
    __shared__ __align__(16) float sv[32][DH];

    const int d0 = (tid >> 4) * 4;          // 16 groups * 4 = 64
    const int e0 = (tid & 15) * 4;

    float acc[4][4];
    #pragma unroll
    for (int i = 0; i < 4; i++)
        #pragma unroll
        for (int j = 0; j < 4; j++) acc[i][j] = 0.f;

    const float* base = g_qkv + (size_t)b * NSEQ * N_QKV;
    const int n_begin = chunk * ROWS_PER_CHUNK;

    for (int n0 = n_begin; n0 < n_begin + ROWS_PER_CHUNK; n0 += 32) {
        // stage 32 rows of k and v (64 floats each): 512 float4, 2 per thread
        #pragma unroll
        for (int i = 0; i < 2; i++) {
            int id = tid + i * 256;          // 0..511
            int r  = id >> 4;                // 0..31
            int c  = (id & 15) * 4;          // 0..60
            size_t off = (size_t)(n0 + r) * N_QKV + h * DH + c;
            *(float4*)&sk[r][c] = *(const float4*)(base + off + INNER);       // k block
            *(float4*)&sv[r][c] = *(const float4*)(base + off + 2 * INNER);   // v block
        }
        __syncthreads();

        // softmax over d for each of the 32 rows: 8 lanes per row
        {
            int r     = tid >> 3;            // 0..31
            int lane8 = tid & 7;             // aligned 8-lane group inside warp
            float vals[8];
            float m = -1e30f;
            #pragma unroll
            for (int j = 0; j < 8; j++) {
                vals[j] = sk[r][lane8 * 8 + j];
                m = fmaxf(m, vals[j]);
            }
            #pragma unroll
            for (int s = 4; s >= 1; s >>= 1)
                m = fmaxf(m, __shfl_xor_sync(0xffffffffu, m, s));
            float sum = 0.f;
            #pragma unroll
            for (int j = 0; j < 8; j++) { vals[j] = __expf(vals[j] - m); sum += vals[j]; }
            #pragma unroll
            for (int s = 4; s >= 1; s >>= 1)
                sum += __shfl_xor_sync(0xffffffffu, sum, s);
            float inv = 1.0f / sum;
            #pragma unroll
            for (int j = 0; j < 8; j++)
                sk[r][lane8 * 8 + j] = vals[j] * inv;
        }
        __syncthreads();

        // rank-1 accumulation: acc[d0..+3][e0..+3] += sk[r][d] * sv[r][e]
        #pragma unroll 4
        for (int r = 0; r < 32; r++) {
            float4 kd = *(const float4*)&sk[r][d0];
            float4 ve = *(const float4*)&sv[r][e0];
            float kdv[4] = {kd.x, kd.y, kd.z, kd.w};
            float vev[4] = {ve.x, ve.y, ve.z, ve.w};
            #pragma unroll
            for (int i = 0; i < 4; i++)
                #pragma unroll
                for (int j = 0; j < 4; j++)
                    acc[i][j] += kdv[i] * vev[j];
        }
        __syncthreads();
    }

    float* out = g_ctxp + ((size_t)chunk * (B*HEADS) + pair) * DH * DH;
    #pragma unroll
    for (int i = 0; i < 4; i++) {
        float4 v = make_float4(acc[i][0], acc[i][1], acc[i][2], acc[i][3]);
        *(float4*)&out[(d0 + i) * DH + e0] = v;
    }
}

// ---------------------------------------------------------------------------
// Attention-apply kernel: attn[b,n, h*64+e] = sum_d q[b,n,h*64+d] * ctx[b,h][d][e]
// grid = (32 pairs, 4096/128 row tiles), block = 256.
// ---------------------------------------------------------------------------
__global__ __launch_bounds__(256) void attn_kernel()
{
    const int pair = blockIdx.x;
    const int b = pair >> 3, h = pair & 7;
    const int n0 = blockIdx.y * 128;
    const int tid = threadIdx.x;

    __shared__ __align__(16) float sctx[DH][DH];     // 16 KB
    __shared__ __align__(16) float sq[128][DH];      // 32 KB

    // sum the NCHUNK partial contexts
    for (int idx = tid; idx < DH * DH; idx += 256) {
        float s = 0.f;
        #pragma unroll
        for (int ch = 0; ch < NCHUNK; ch++)
            s += g_ctxp[((size_t)ch * (B*HEADS) + pair) * DH * DH + idx];
        sctx[idx >> 6][idx & 63] = s;
    }

    // stage 128 q rows (64 floats each): 2048 float4, 8 per thread
    const float* qbase = g_qkv + (size_t)b * NSEQ * N_QKV + h * DH;
    #pragma unroll
    for (int i = 0; i < 8; i++) {
        int id = tid + i * 256;              // 0..2047
        int r  = id >> 4;                    // 0..127
        int c  = (id & 15) * 4;
        *(float4*)&sq[r][c] =
            *(const float4*)(qbase + (size_t)(n0 + r) * N_QKV + c);
    }
    __syncthreads();

    // thread computes 8 rows x 4 cols
    const int e0 = (tid & 15) * 4;           // 16 e-groups
    const int rg = tid >> 4;                 // 16 row-groups; rows rg + 16*k
    float acc[8][4];
    #pragma unroll
    for (int i = 0; i < 8; i++)
        #pragma unroll
        for (int j = 0; j < 4; j++) acc[i][j] = 0.f;

    #pragma unroll 8
    for (int d = 0; d < DH; d++) {
        float4 c4 = *(const float4*)&sctx[d][e0];
        float cv[4] = {c4.x, c4.y, c4.z, c4.w};
        #pragma unroll
        for (int i = 0; i < 8; i++) {
            float a = sq[rg + 16 * i][d];
            #pragma unroll
            for (int j = 0; j < 4; j++)
                acc[i][j] += a * cv[j];
        }
    }

    float* obase = g_attn + (size_t)(b * NSEQ + n0) * INNER + h * DH;
    #pragma unroll
    for (int i = 0; i < 8; i++) {
        int r = rg + 16 * i;
        float4 v = make_float4(acc[i][0], acc[i][1], acc[i][2], acc[i][3]);
        *(float4*)(obase + (size_t)r * INNER + e0) = v;
    }
}

// ---------------------------------------------------------------------------
extern "C" void kernel_launch(void* const* d_in, const int* in_sizes, int n_in,
                              void* d_out, int out_size)
{
    const float* x     = (const float*)d_in[0];   // [4,4096,1024]
    const float* w_qkv = (const float*)d_in[1];   // [1536,1024]
    const float* w_out = (const float*)d_in[2];   // [1024,512]
    const float* b_out = (const float*)d_in[3];   // [1024]
    float* out = (float*)d_out;                   // [4,4096,1024]

    float *qkv_ptr, *attn_ptr;
    cudaGetSymbolAddress((void**)&qkv_ptr,  g_qkv);
    cudaGetSymbolAddress((void**)&attn_ptr, g_attn);

    // 1) QKV projection: [16384,1536] = x @ w_qkv^T
    sgemm_nt<<<dim3(N_QKV / BN, M_ROWS / BM), 256>>>(
        x, w_qkv, qkv_ptr, nullptr, M_ROWS, N_QKV, DIM);

    // 2) softmax(k) + context partials
    ctx_kernel<<<dim3(B * HEADS, NCHUNK), 256>>>();

    // 3) q @ context -> attn [16384, 512]
    attn_kernel<<<dim3(B * HEADS, NSEQ / 128), 256>>>();

    // 4) output projection + bias: [16384,1024] = attn @ w_out^T + b_out
    sgemm_nt<<<dim3(DIM / BN, M_ROWS / BM), 256>>>(
        attn_ptr, w_out, out, b_out, M_ROWS, DIM, INNER);
}

// round 4
// speedup vs baseline: 1.3254x; 1.3254x over previous
#include <cuda_runtime.h>
#include <cuda_bf16.h>
#include <mma.h>
#include <cstdint>

using namespace nvcuda;

// Problem constants
#define B       4
#define NSEQ    4096
#define DIM     1024
#define HEADS   8
#define DH      64
#define INNER   512          // HEADS*DH
#define M_ROWS  (B*NSEQ)     // 16384
#define N_QKV   (3*INNER)    // 1536
#define NCHUNK  8            // split-K chunks for context
#define ROWS_PER_CHUNK (NSEQ/NCHUNK)  // 512

// Scratch (device globals; no allocation allowed)
__device__ float g_qkv [(size_t)M_ROWS * N_QKV];          // ~100.7 MB
__device__ float g_ctxp[NCHUNK * B*HEADS * DH * DH];      // 4 MB partial contexts
__device__ float g_attn[(size_t)M_ROWS * INNER];          // ~33.5 MB

// ---------------------------------------------------------------------------
// TF32 tensor-core GEMM (NT): C[M,N] = A[M,K] @ Bm[N,K]^T (+ bias[N])
// BM=BN=128, BK=32, 256 threads (8 warps as 2x4), warp tile 64x32,
// wmma 16x16x8 tf32 fragments, fp32 accumulate.
// Requires M%128==0, N%128==0, K%32==0.
// ---------------------------------------------------------------------------
#define BKP 40   // smem row stride (pad vs 32 for bank spread; multiple of 4)

__global__ __launch_bounds__(256) void tf32_gemm_nt(
    const float* __restrict__ A,
    const float* __restrict__ Bm,
    float* __restrict__ C,
    const float* __restrict__ bias,
    int M, int N, int K)
{
    __shared__ __align__(16) float As[128][BKP];
    __shared__ __align__(16) float Bs[128][BKP];
    __shared__ __align__(16) float biasT[128][8];

    const int bm  = blockIdx.y * 128;
    const int bn  = blockIdx.x * 128;
    const int tid = threadIdx.x;
    const int wid = tid >> 5;
    const int wm  = (wid >> 2) * 64;   // warp row offset: 0 or 64
    const int wn  = (wid & 3) * 32;    // warp col offset: 0..96

    wmma::fragment<wmma::accumulator, 16, 16, 8, float> acc[4][2];
    #pragma unroll
    for (int mi = 0; mi < 4; mi++)
        #pragma unroll
        for (int ni = 0; ni < 2; ni++)
            wmma::fill_fragment(acc[mi][ni], 0.0f);

    // ---- fold bias into accumulators: acc += ones(0.125) @ biasT (8 k-terms)
    if (bias) {
        if (tid < 128) {
            float bv = bias[bn + tid];
            #pragma unroll
            for (int k = 0; k < 8; k++) biasT[tid][k] = bv;
        }
        __syncthreads();
        wmma::fragment<wmma::matrix_a, 16, 16, 8, wmma::precision::tf32,
                       wmma::row_major> af;
        wmma::fill_fragment(af, wmma::__float_to_tf32(0.125f));
        #pragma unroll
        for (int ni = 0; ni < 2; ni++) {
            wmma::fragment<wmma::matrix_b, 16, 16, 8, wmma::precision::tf32,
                           wmma::col_major> bf;
            wmma::load_matrix_sync(bf, &biasT[wn + ni * 16][0], 8);
            #pragma unroll
            for (int t = 0; t < bf.num_elements; t++)
                bf.x[t] = wmma::__float_to_tf32(bf.x[t]);
            #pragma unroll
            for (int mi = 0; mi < 4; mi++)
                wmma::mma_sync(acc[mi][ni], af, bf, acc[mi][ni]);
        }
        __syncthreads();
    }

    const float* Aptr = A  + (size_t)bm * K;
    const float* Bptr = Bm + (size_t)bn * K;

    for (int k0 = 0; k0 < K; k0 += 32) {
        // stage 128x32 tiles of A and B, converting to tf32 once here.
        // 1024 float4 per operand, 4 per thread.
        #pragma unroll
        for (int i = 0; i < 4; i++) {
            int id = tid + i * 256;          // 0..1023
            int r  = id >> 3;                // 0..127
            int c  = (id & 7) * 4;           // 0..28
            float4 av = *(const float4*)(Aptr + (size_t)r * K + k0 + c);
            As[r][c+0] = wmma::__float_to_tf32(av.x);
            As[r][c+1] = wmma::__float_to_tf32(av.y);
            As[r][c+2] = wmma::__float_to_tf32(av.z);
            As[r][c+3] = wmma::__float_to_tf32(av.w);
            float4 bv = *(const float4*)(Bptr + (size_t)r * K + k0 + c);
            Bs[r][c+0] = wmma::__float_to_tf32(bv.x);
            Bs[r][c+1] = wmma::__float_to_tf32(bv.y);
            Bs[r][c+2] = wmma::__float_to_tf32(bv.z);
            Bs[r][c+3] = wmma::__float_to_tf32(bv.w);
        }
        __syncthreads();

        #pragma unroll
        for (int ks = 0; ks < 4; ks++) {
            wmma::fragment<wmma::matrix_a, 16, 16, 8, wmma::precision::tf32,
                           wmma::row_major> af[4];
            wmma::fragment<wmma::matrix_b, 16, 16, 8, wmma::precision::tf32,
                           wmma::col_major> bf[2];
            #pragma unroll
            for (int mi = 0; mi < 4; mi++)
                wmma::load_matrix_sync(af[mi], &As[wm + mi * 16][ks * 8], BKP);
            #pragma unroll
            for (int ni = 0; ni < 2; ni++)
                wmma::load_matrix_sync(bf[ni], &Bs[wn + ni * 16][ks * 8], BKP);
            #pragma unroll
            for (int mi = 0; mi < 4; mi++)
                #pragma unroll
                for (int ni = 0; ni < 2; ni++)
                    wmma::mma_sync(acc[mi][ni], af[mi], bf[ni], acc[mi][ni]);
        }
        __syncthreads();
    }

    #pragma unroll
    for (int mi = 0; mi < 4; mi++)
        #pragma unroll
        for (int ni = 0; ni < 2; ni++)
            wmma::store_matrix_sync(
                &C[(size_t)(bm + wm + mi * 16) * N + bn + wn + ni * 16],
                acc[mi][ni], N, wmma::mem_row_major);
}

// ---------------------------------------------------------------------------
// Context kernel: for each (b,h), ctx[d][e] = sum_n softmax(k[n,:])[d] * v[n,e]
// Split over n into NCHUNK chunks; each block writes a deterministic partial.
// grid = (32 pairs, NCHUNK), block = 256.
// ---------------------------------------------------------------------------
__global__ __launch_bounds__(256) void ctx_kernel()
{
    const int pair  = blockIdx.x;           // b*HEADS + h
    const int chunk = blockIdx.y;
    const int b = pair >> 3, h = pair & 7;
    const int tid = threadIdx.x;

    __shared__ __align__(16) float sk[32][DH];
    __shared__ __align__(16) float sv[32][DH];

    const int d0 = (tid >> 4) * 4;          // 16 groups * 4 = 64
    const int e0 = (tid & 15) * 4;

    float acc[4][4];
    #pragma unroll
    for (int i = 0; i < 4; i++)
        #pragma unroll
        for (int j = 0; j < 4; j++) acc[i][j] = 0.f;

    const float* base = g_qkv + (size_t)b * NSEQ * N_QKV;
    const int n_begin = chunk * ROWS_PER_CHUNK;

    for (int n0 = n_begin; n0 < n_begin + ROWS_PER_CHUNK; n0 += 32) {
        #pragma unroll
        for (int i = 0; i < 2; i++) {
            int id = tid + i * 256;          // 0..511
            int r  = id >> 4;                // 0..31
            int c  = (id & 15) * 4;          // 0..60
            size_t off = (size_t)(n0 + r) * N_QKV + h * DH + c;
            *(float4*)&sk[r][c] = *(const float4*)(base + off + INNER);       // k
            *(float4*)&sv[r][c] = *(const float4*)(base + off + 2 * INNER);   // v
        }
        __syncthreads();

        // softmax over d for each of the 32 rows: 8 lanes per row
        {
            int r     = tid >> 3;
            int lane8 = tid & 7;
            float vals[8];
            float m = -1e30f;
            #pragma unroll
            for (int j = 0; j < 8; j++) {
                vals[j] = sk[r][lane8 * 8 + j];
                m = fmaxf(m, vals[j]);
            }
            #pragma unroll
            for (int s = 4; s >= 1; s >>= 1)
                m = fmaxf(m, __shfl_xor_sync(0xffffffffu, m, s));
            float sum = 0.f;
            #pragma unroll
            for (int j = 0; j < 8; j++) { vals[j] = __expf(vals[j] - m); sum += vals[j]; }
            #pragma unroll
            for (int s = 4; s >= 1; s >>= 1)
                sum += __shfl_xor_sync(0xffffffffu, sum, s);
            float inv = 1.0f / sum;
            #pragma unroll
            for (int j = 0; j < 8; j++)
                sk[r][lane8 * 8 + j] = vals[j] * inv;
        }
        __syncthreads();

        #pragma unroll 4
        for (int r = 0; r < 32; r++) {
            float4 kd = *(const float4*)&sk[r][d0];
            float4 ve = *(const float4*)&sv[r][e0];
            float kdv[4] = {kd.x, kd.y, kd.z, kd.w};
            float vev[4] = {ve.x, ve.y, ve.z, ve.w};
            #pragma unroll
            for (int i = 0; i < 4; i++)
                #pragma unroll
                for (int j = 0; j < 4; j++)
                    acc[i][j] += kdv[i] * vev[j];
        }
        __syncthreads();
    }

    float* out = g_ctxp + ((size_t)chunk * (B*HEADS) + pair) * DH * DH;
    #pragma unroll
    for (int i = 0; i < 4; i++) {
        float4 v = make_float4(acc[i][0], acc[i][1], acc[i][2], acc[i][3]);
        *(float4*)&out[(d0 + i) * DH + e0] = v;
    }
}

// ---------------------------------------------------------------------------
// Attention-apply kernel: attn[b,n,h*64+e] = sum_d q[b,n,h*64+d] * ctx[b,h][d][e]
// grid = (32 pairs, 4096/128 row tiles), block = 256.
// ---------------------------------------------------------------------------
__global__ __launch_bounds__(256) void attn_kernel()
{
    const int pair = blockIdx.x;
    const int b = pair >> 3, h = pair & 7;
    const int n0 = blockIdx.y * 128;
    const int tid = threadIdx.x;

    __shared__ __align__(16) float sctx[DH][DH];     // 16 KB
    __shared__ __align__(16) float sq[128][DH];      // 32 KB

    for (int idx = tid; idx < DH * DH; idx += 256) {
        float s = 0.f;
        #pragma unroll
        for (int ch = 0; ch < NCHUNK; ch++)
            s += g_ctxp[((size_t)ch * (B*HEADS) + pair) * DH * DH + idx];
        sctx[idx >> 6][idx & 63] = s;
    }

    const float* qbase = g_qkv + (size_t)b * NSEQ * N_QKV + h * DH;
    #pragma unroll
    for (int i = 0; i < 8; i++) {
        int id = tid + i * 256;              // 0..2047
        int r  = id >> 4;                    // 0..127
        int c  = (id & 15) * 4;
        *(float4*)&sq[r][c] =
            *(const float4*)(qbase + (size_t)(n0 + r) * N_QKV + c);
    }
    __syncthreads();

    const int e0 = (tid & 15) * 4;
    const int rg = tid >> 4;
    float acc[8][4];
    #pragma unroll
    for (int i = 0; i < 8; i++)
        #pragma unroll
        for (int j = 0; j < 4; j++) acc[i][j] = 0.f;

    #pragma unroll 8
    for (int d = 0; d < DH; d++) {
        float4 c4 = *(const float4*)&sctx[d][e0];
        float cv[4] = {c4.x, c4.y, c4.z, c4.w};
        #pragma unroll
        for (int i = 0; i < 8; i++) {
            float a = sq[rg + 16 * i][d];
            #pragma unroll
            for (int j = 0; j < 4; j++)
                acc[i][j] += a * cv[j];
        }
    }

    float* obase = g_attn + (size_t)(b * NSEQ + n0) * INNER + h * DH;
    #pragma unroll
    for (int i = 0; i < 8; i++) {
        int r = rg + 16 * i;
        float4 v = make_float4(acc[i][0], acc[i][1], acc[i][2], acc[i][3]);
        *(float4*)(obase + (size_t)r * INNER + e0) = v;
    }
}

// ---------------------------------------------------------------------------
extern "C" void kernel_launch(void* const* d_in, const int* in_sizes, int n_in,
                              void* d_out, int out_size)
{
    const float* x     = (const float*)d_in[0];   // [4,4096,1024]
    const float* w_qkv = (const float*)d_in[1];   // [1536,1024]
    const float* w_out = (const float*)d_in[2];   // [1024,512]
    const float* b_out = (const float*)d_in[3];   // [1024]
    float* out = (float*)d_out;                   // [4,4096,1024]

    float *qkv_ptr, *attn_ptr;
    cudaGetSymbolAddress((void**)&qkv_ptr,  g_qkv);
    cudaGetSymbolAddress((void**)&attn_ptr, g_attn);

    // 1) QKV projection: [16384,1536] = x @ w_qkv^T   (tensor cores, tf32)
    tf32_gemm_nt<<<dim3(N_QKV / 128, M_ROWS / 128), 256>>>(
        x, w_qkv, qkv_ptr, nullptr, M_ROWS, N_QKV, DIM);

    // 2) softmax(k) + context partials
    ctx_kernel<<<dim3(B * HEADS, NCHUNK), 256>>>();

    // 3) q @ context -> attn [16384, 512]
    attn_kernel<<<dim3(B * HEADS, NSEQ / 128), 256>>>();

    // 4) output projection + bias: [16384,1024] = attn @ w_out^T + b_out
    tf32_gemm_nt<<<dim3(DIM / 128, M_ROWS / 128), 256>>>(
        attn_ptr, w_out, out, b_out, M_ROWS, DIM, INNER);
}